// round 3
// baseline (speedup 1.0000x reference)
#include <cuda_runtime.h>
#include <math.h>

#define NROWS 102400      // BS * N_AGENTS
#define HID   128
#define NAG   50
#define NBATCH 2048
#define QSIZE (NROWS * 8)

// Scratch (static device memory; allocation-free kernel_launch)
__device__ float g_bufA[NROWS * 128];
__device__ float g_bufB[NROWS * 128];
__device__ float g_gi[NROWS * 384];
__device__ float g_gh[NROWS * 384];

// ---------------------------------------------------------------------------
// C[M x N] = A[M x 128] @ W[N x 128]^T  (+ optional bias[N])
// BM=64, BN=64, BK=16, 256 threads, 4x4 register tile per thread.
// ---------------------------------------------------------------------------
__global__ void gemm128(const float* __restrict__ A, const float* __restrict__ W,
                        const float* __restrict__ bias, float* __restrict__ C, int N) {
    __shared__ float As[16][64];
    __shared__ float Bs[16][64];
    int tid = threadIdx.x;
    int m0 = blockIdx.x * 64;
    int n0 = blockIdx.y * 64;
    int lr = tid >> 2;          // 0..63  (row within tile for loads)
    int lk = (tid & 3) << 2;    // 0,4,8,12 (k offset for float4 load)
    int tx = tid & 15;          // 0..15 (output col group)
    int ty = tid >> 4;          // 0..15 (output row group)

    float acc[4][4];
#pragma unroll
    for (int i = 0; i < 4; i++)
#pragma unroll
        for (int j = 0; j < 4; j++) acc[i][j] = 0.f;

    const float* Ag = A + (size_t)(m0 + lr) * 128 + lk;
    const float* Wg = W + (size_t)(n0 + lr) * 128 + lk;

    for (int k0 = 0; k0 < 128; k0 += 16) {
        float4 av = *(const float4*)(Ag + k0);
        float4 wv = *(const float4*)(Wg + k0);
        __syncthreads();
        As[lk + 0][lr] = av.x; As[lk + 1][lr] = av.y;
        As[lk + 2][lr] = av.z; As[lk + 3][lr] = av.w;
        Bs[lk + 0][lr] = wv.x; Bs[lk + 1][lr] = wv.y;
        Bs[lk + 2][lr] = wv.z; Bs[lk + 3][lr] = wv.w;
        __syncthreads();
#pragma unroll
        for (int kk = 0; kk < 16; kk++) {
            float4 a4 = *(const float4*)&As[kk][ty << 2];
            float4 b4 = *(const float4*)&Bs[kk][tx << 2];
            float a[4] = {a4.x, a4.y, a4.z, a4.w};
            float b[4] = {b4.x, b4.y, b4.z, b4.w};
#pragma unroll
            for (int i = 0; i < 4; i++)
#pragma unroll
                for (int j = 0; j < 4; j++) acc[i][j] += a[i] * b[j];
        }
    }

#pragma unroll
    for (int i = 0; i < 4; i++) {
        size_t row = (size_t)(m0 + (ty << 2) + i);
        int col = n0 + (tx << 2);
        float4 v;
        v.x = acc[i][0]; v.y = acc[i][1]; v.z = acc[i][2]; v.w = acc[i][3];
        if (bias) {
            v.x += bias[col + 0]; v.y += bias[col + 1];
            v.z += bias[col + 2]; v.w += bias[col + 3];
        }
        *(float4*)&C[row * N + col] = v;
    }
}

// ---------------------------------------------------------------------------
// Per-batch-sample: out[b] = relu(normAdj(50x50) @ Y[b](50x128) + bias[128])
// One CTA per batch sample, 128 threads (one per hidden dim), 50 accumulators.
// ---------------------------------------------------------------------------
__global__ void adj_relu_kernel(const float* __restrict__ Y, const float* __restrict__ adj,
                                const float* __restrict__ bias, float* __restrict__ out) {
    __shared__ float A_s[50][52];   // padded to 52 (mult of 4) for float4 loads
    __shared__ float Yb[52][128];   // rows 50,51 zero-padded
    int b = blockIdx.x;
    int tid = threadIdx.x;          // 128

    for (int i = tid; i < 50 * 52; i += 128) {
        int r = i / 52, c = i - r * 52;
        A_s[r][c] = (c < 50) ? adj[r * 50 + c] : 0.f;
    }
    const float* Yg = Y + (size_t)b * NAG * 128;
    for (int i = tid; i < 52 * 128; i += 128) {
        int r = i >> 7, c = i & 127;
        Yb[r][c] = (r < 50) ? Yg[r * 128 + c] : 0.f;
    }
    __syncthreads();

    int d = tid;
    float acc[50];
#pragma unroll
    for (int i = 0; i < 50; i++) acc[i] = 0.f;

#pragma unroll 1
    for (int j = 0; j < 52; j += 4) {
        float y0 = Yb[j + 0][d];
        float y1 = Yb[j + 1][d];
        float y2 = Yb[j + 2][d];
        float y3 = Yb[j + 3][d];
#pragma unroll
        for (int i = 0; i < 50; i++) {
            float4 a = *(const float4*)&A_s[i][j];
            acc[i] += a.x * y0 + a.y * y1 + a.z * y2 + a.w * y3;
        }
    }

    float bv = bias[d];
    float* og = out + (size_t)b * NAG * 128;
#pragma unroll 1
    for (int i = 0; i < 50; i++)
        og[i * 128 + d] = fmaxf(acc[i] + bv, 0.f);
}

// ---------------------------------------------------------------------------
// GRU gate combine: h = (1-z)*n + z*h_in
// ---------------------------------------------------------------------------
__global__ void gru_kernel(const float* __restrict__ gi, const float* __restrict__ gh,
                           const float* __restrict__ h_in, float* __restrict__ h_out) {
    int idx = blockIdx.x * blockDim.x + threadIdx.x;   // < NROWS*128 exact
    int r = idx >> 7, c = idx & 127;
    size_t base = (size_t)r * 384;
    float ir = gi[base + c], iz = gi[base + 128 + c], in_ = gi[base + 256 + c];
    float hr = gh[base + c], hz = gh[base + 128 + c], hn = gh[base + 256 + c];
    float hv = h_in[idx];
    float rg = 1.f / (1.f + expf(-(ir + hr)));
    float zg = 1.f / (1.f + expf(-(iz + hz)));
    float ng = tanhf(in_ + rg * hn);
    h_out[idx] = (1.f - zg) * ng + zg * hv;
}

// ---------------------------------------------------------------------------
// q[Mx8] = H[Mx128] @ Wfc2[8x128]^T + b[8].  32 rows per CTA, 256 threads.
// ---------------------------------------------------------------------------
__global__ void fc2_kernel(const float* __restrict__ H, const float* __restrict__ W,
                           const float* __restrict__ bias, float* __restrict__ Q) {
    __shared__ float Hs[32][132];
    __shared__ float Ws[8][132];
    int tid = threadIdx.x;
    size_t r0 = (size_t)blockIdx.x * 32;

    for (int i = tid; i < 32 * 32; i += 256) {  // float4 units
        int r = i >> 5, c4 = (i & 31) << 2;
        *(float4*)&Hs[r][c4] = *(const float4*)&H[(r0 + r) * 128 + c4];
    }
    for (int i = tid; i < 8 * 32; i += 256) {
        int r = i >> 5, c4 = (i & 31) << 2;
        *(float4*)&Ws[r][c4] = *(const float4*)&W[r * 128 + c4];
    }
    __syncthreads();

    int rl = tid >> 3, a = tid & 7;
    float acc = 0.f;
#pragma unroll
    for (int k = 0; k < 128; k++) acc += Hs[rl][k] * Ws[a][k];
    Q[(r0 + rl) * 8 + a] = acc + bias[a];
}

// ---------------------------------------------------------------------------
extern "C" void kernel_launch(void* const* d_in, const int* in_sizes, int n_in,
                              void* d_out, int out_size) {
    const float* inputs   = (const float*)d_in[0];   // (102400, 128)
    const float* hidden   = (const float*)d_in[1];   // (2048, 50, 128) -> (102400,128)
    const float* norm_adj = (const float*)d_in[2];   // (50, 50)
    const float* w_gcn    = (const float*)d_in[3];   // (128, 128)
    const float* b_gcn    = (const float*)d_in[4];   // (128,)
    const float* w_ih     = (const float*)d_in[5];   // (384, 128)
    const float* b_ih     = (const float*)d_in[6];   // (384,)
    const float* w_hh     = (const float*)d_in[7];   // (384, 128)
    const float* b_hh     = (const float*)d_in[8];   // (384,)
    const float* w_fc2    = (const float*)d_in[9];   // (8, 128)
    const float* b_fc2    = (const float*)d_in[10];  // (8,)

    float* out = (float*)d_out;
    float* q_out = out;               // (102400, 8)
    float* h_out = out + QSIZE;       // (102400, 128)

    float *bufA, *bufB, *gi, *gh;
    cudaGetSymbolAddress((void**)&bufA, g_bufA);
    cudaGetSymbolAddress((void**)&bufB, g_bufB);
    cudaGetSymbolAddress((void**)&gi, g_gi);
    cudaGetSymbolAddress((void**)&gh, g_gh);

    dim3 gemmGridH(NROWS / 64, 128 / 64);   // N=128
    dim3 gemmGridG(NROWS / 64, 384 / 64);   // N=384

    // GCN pass 1
    gemm128<<<gemmGridH, 256>>>(inputs, w_gcn, nullptr, bufA, 128);
    adj_relu_kernel<<<NBATCH, 128>>>(bufA, norm_adj, b_gcn, bufB);
    // GCN pass 2
    gemm128<<<gemmGridH, 256>>>(bufB, w_gcn, nullptr, bufA, 128);
    adj_relu_kernel<<<NBATCH, 128>>>(bufA, norm_adj, b_gcn, bufB);
    // GCN pass 3
    gemm128<<<gemmGridH, 256>>>(bufB, w_gcn, nullptr, bufA, 128);
    adj_relu_kernel<<<NBATCH, 128>>>(bufA, norm_adj, b_gcn, bufB);   // bufB = x_c

    // GRU gates
    gemm128<<<gemmGridG, 256>>>(bufB, w_ih, b_ih, gi, 384);
    gemm128<<<gemmGridG, 256>>>(hidden, w_hh, b_hh, gh, 384);
    gru_kernel<<<(NROWS * 128) / 256, 256>>>(gi, gh, hidden, h_out);

    // fc2 -> q
    fc2_kernel<<<NROWS / 32, 256>>>(h_out, w_fc2, b_fc2, q_out);
}

// round 6
// speedup vs baseline: 1.6372x; 1.6372x over previous
#include <cuda_runtime.h>
#include <cuda_bf16.h>
#include <cstdint>
#include <math.h>

#define NROWS 102400      // BS * N_AGENTS
#define NBATCH 2048
#define QSIZE (NROWS * 8)

// ---------------- static scratch (allocation-free) ----------------
// Split layout: row-major [rows][256] bf16, cols 0..127 = hi, 128..255 = lo.
__device__ __nv_bfloat16  g_xs[NROWS * 256];     // x (GCN activations), split
__device__ __nv_bfloat16  g_hs[NROWS * 256];     // hidden_state, split
__device__ float          g_bufY[NROWS * 128];   // GCN gemm output (fp32)
__device__ float          g_gi[NROWS * 384];
__device__ float          g_gh[NROWS * 384];
__device__ __nv_bfloat16  g_wgs[128 * 256];      // w_gcn split
__device__ __nv_bfloat16  g_wihs[384 * 256];     // w_ih split
__device__ __nv_bfloat16  g_whhs[384 * 256];     // w_hh split

// smem tile geometry for gemm_hmma: K=384 (3 compensation segments) + 8 pad
#define LDS_K 392
#define TILE_BF16 (128 * LDS_K)
#define GEMM_SMEM (2 * TILE_BF16 * 2)    // 200704 bytes

// ---------------------------------------------------------------------------
// C[M x (nchunks*128)] = A[M x 128] @ W^T via HMMA bf16, error-compensated.
// A,W stored globally as [rows][256] = [hi|lo]. In smem we assemble K=384:
//   k[  0..128): Ahi * Bhi
//   k[128..256): Alo * Bhi
//   k[256..384): Ahi * Blo
// -> full first-order compensation; residual ~2^-16 (Alo*Blo omitted).
// BM=128, BN=128 per chunk, 256 threads, warp grid 4(m) x 2(n), warp tile 32x64.
// ---------------------------------------------------------------------------
__global__ void __launch_bounds__(256)
gemm_hmma(const __nv_bfloat16* __restrict__ A, const __nv_bfloat16* __restrict__ W,
          const float* __restrict__ bias, float* __restrict__ out, int ldc, int nchunks) {
    extern __shared__ __nv_bfloat16 sm[];
    __nv_bfloat16* As = sm;               // [128][LDS_K]
    __nv_bfloat16* Bs = sm + TILE_BF16;   // [128][LDS_K]

    int tid = threadIdx.x;
    int wid = tid >> 5, lane = tid & 31;
    int grp = lane >> 2, tig = lane & 3;
    int warp_m = wid & 3, warp_n = wid >> 2;
    int mrow0 = warp_m * 32;
    int ncol0 = warp_n * 64;
    size_t m0 = (size_t)blockIdx.x * 128;

    // load A tile: 48 uint4 per row (cols 0..31 = global hi|lo, 32..47 = hi again)
    {
        const uint4* ag = reinterpret_cast<const uint4*>(A + m0 * 256);  // 32 uint4/row
        for (int i = tid; i < 128 * 48; i += 256) {
            int r = i / 48, c = i - r * 48;
            int cs = (c < 32) ? c : (c - 32);
            *reinterpret_cast<uint4*>(&As[r * LDS_K + c * 8]) = ag[r * 32 + cs];
        }
    }

    for (int j = 0; j < nchunks; j++) {
        // load B chunk rows j*128..: cols 0..15 = hi, 16..31 = hi again, 32..47 = lo
        const uint4* bg = reinterpret_cast<const uint4*>(W + (size_t)j * 128 * 256);
        for (int i = tid; i < 128 * 48; i += 256) {
            int r = i / 48, c = i - r * 48;
            int cs = (c < 16) ? c : (c - 16);   // 16..31 -> hi(0..15), 32..47 -> lo(16..31)
            *reinterpret_cast<uint4*>(&Bs[r * LDS_K + c * 8]) = bg[r * 32 + cs];
        }
        __syncthreads();

        float acc[2][8][4];
#pragma unroll
        for (int mt = 0; mt < 2; mt++)
#pragma unroll
            for (int nt = 0; nt < 8; nt++)
#pragma unroll
                for (int q = 0; q < 4; q++) acc[mt][nt][q] = 0.f;

#pragma unroll
        for (int ks = 0; ks < 24; ks++) {
            int k0 = ks * 16;
            uint32_t afr[2][4];
#pragma unroll
            for (int mt = 0; mt < 2; mt++) {
                int r = mrow0 + mt * 16 + grp;
                const uint32_t* p0 = reinterpret_cast<const uint32_t*>(&As[r * LDS_K + k0 + tig * 2]);
                const uint32_t* p1 = reinterpret_cast<const uint32_t*>(&As[(r + 8) * LDS_K + k0 + tig * 2]);
                afr[mt][0] = p0[0];
                afr[mt][1] = p1[0];
                afr[mt][2] = p0[4];   // +8 bf16
                afr[mt][3] = p1[4];
            }
            uint32_t bfr[8][2];
#pragma unroll
            for (int nt = 0; nt < 8; nt++) {
                int n = ncol0 + nt * 8 + grp;
                const uint32_t* q = reinterpret_cast<const uint32_t*>(&Bs[n * LDS_K + k0 + tig * 2]);
                bfr[nt][0] = q[0];
                bfr[nt][1] = q[4];
            }
#pragma unroll
            for (int mt = 0; mt < 2; mt++)
#pragma unroll
                for (int nt = 0; nt < 8; nt++)
                    asm volatile(
                        "mma.sync.aligned.m16n8k16.row.col.f32.bf16.bf16.f32 "
                        "{%0,%1,%2,%3}, {%4,%5,%6,%7}, {%8,%9}, {%0,%1,%2,%3};"
                        : "+f"(acc[mt][nt][0]), "+f"(acc[mt][nt][1]),
                          "+f"(acc[mt][nt][2]), "+f"(acc[mt][nt][3])
                        : "r"(afr[mt][0]), "r"(afr[mt][1]), "r"(afr[mt][2]), "r"(afr[mt][3]),
                          "r"(bfr[nt][0]), "r"(bfr[nt][1]));
        }

        // epilogue
        int cbase = j * 128;
#pragma unroll
        for (int mt = 0; mt < 2; mt++) {
#pragma unroll
            for (int nt = 0; nt < 8; nt++) {
                size_t row = m0 + mrow0 + mt * 16 + grp;
                int col = cbase + ncol0 + nt * 8 + tig * 2;
                float b0 = 0.f, b1 = 0.f;
                if (bias) { b0 = bias[col]; b1 = bias[col + 1]; }
                float2 v0 = {acc[mt][nt][0] + b0, acc[mt][nt][1] + b1};
                float2 v1 = {acc[mt][nt][2] + b0, acc[mt][nt][3] + b1};
                *reinterpret_cast<float2*>(&out[row * ldc + col]) = v0;
                *reinterpret_cast<float2*>(&out[(row + 8) * ldc + col]) = v1;
            }
        }
        __syncthreads();   // before next chunk overwrites Bs
    }
}

// ---------------------------------------------------------------------------
// Per-sample: X = relu(normAdj(50x50) @ Y_b(50x128) + b), fused hi|lo split out.
// 512 threads: 4 groups x 13 rows, one hidden dim per thread.
// ---------------------------------------------------------------------------
__global__ void adj_relu_cvt(const float* __restrict__ Y, const float* __restrict__ adj,
                             const float* __restrict__ bias,
                             __nv_bfloat16* __restrict__ outS) {
    __shared__ float A_s[52][52];
    __shared__ float Yb[52][128];
    int b = blockIdx.x, tid = threadIdx.x;

    for (int i = tid; i < 52 * 52; i += 512) {
        int r = i / 52, c = i - r * 52;
        A_s[r][c] = (r < 50 && c < 50) ? adj[r * 50 + c] : 0.f;
    }
    const float* Yg = Y + (size_t)b * 6400;
    for (int i = tid; i < 52 * 128; i += 512) {
        int r = i >> 7, c = i & 127;
        Yb[r][c] = (r < 50) ? Yg[r * 128 + c] : 0.f;
    }
    __syncthreads();

    int g = tid >> 7, d = tid & 127;
    int i0 = g * 13;
    float acc[13];
#pragma unroll
    for (int i = 0; i < 13; i++) acc[i] = 0.f;

#pragma unroll 1
    for (int j = 0; j < 52; j += 4) {
        float y0 = Yb[j + 0][d], y1 = Yb[j + 1][d];
        float y2 = Yb[j + 2][d], y3 = Yb[j + 3][d];
#pragma unroll
        for (int i = 0; i < 13; i++) {
            float4 a = *reinterpret_cast<const float4*>(&A_s[i0 + i][j]);
            acc[i] += a.x * y0 + a.y * y1 + a.z * y2 + a.w * y3;
        }
    }

    float bv = bias[d];
    __nv_bfloat16* os = outS + (size_t)b * 50 * 256;
#pragma unroll
    for (int i = 0; i < 13; i++) {
        int row = i0 + i;
        if (row < 50) {
            float v = fmaxf(acc[i] + bv, 0.f);
            __nv_bfloat16 h = __float2bfloat16(v);
            os[row * 256 + d]       = h;
            os[row * 256 + 128 + d] = __float2bfloat16(v - __bfloat162float(h));
        }
    }
}

// ---------------------------------------------------------------------------
// fp32 [rows][128] -> bf16 [rows][256] (hi|lo). i indexes float4s (32 per row).
// ---------------------------------------------------------------------------
__global__ void cvt_split(const float* __restrict__ in, __nv_bfloat16* __restrict__ outS,
                          int n4) {
    int i = blockIdx.x * blockDim.x + threadIdx.x;
    if (i >= n4) return;
    float4 v = reinterpret_cast<const float4*>(in)[i];
    int row = i >> 5, c4 = (i & 31) << 2;
    __nv_bfloat16 h0 = __float2bfloat16(v.x), h1 = __float2bfloat16(v.y);
    __nv_bfloat16 h2 = __float2bfloat16(v.z), h3 = __float2bfloat16(v.w);
    __nv_bfloat162 H0{h0, h1}, H1{h2, h3};
    __nv_bfloat162 L0{__float2bfloat16(v.x - __bfloat162float(h0)),
                      __float2bfloat16(v.y - __bfloat162float(h1))};
    __nv_bfloat162 L1{__float2bfloat16(v.z - __bfloat162float(h2)),
                      __float2bfloat16(v.w - __bfloat162float(h3))};
    __nv_bfloat16* base = outS + (size_t)row * 256;
    *reinterpret_cast<__nv_bfloat162*>(base + c4)           = H0;
    *reinterpret_cast<__nv_bfloat162*>(base + c4 + 2)       = H1;
    *reinterpret_cast<__nv_bfloat162*>(base + 128 + c4)     = L0;
    *reinterpret_cast<__nv_bfloat162*>(base + 128 + c4 + 2) = L1;
}

// ---------------------------------------------------------------------------
// GRU gate combine: h = (1-z)*n + z*h_in
// ---------------------------------------------------------------------------
__global__ void gru_kernel(const float* __restrict__ gi, const float* __restrict__ gh,
                           const float* __restrict__ h_in, float* __restrict__ h_out) {
    int idx = blockIdx.x * blockDim.x + threadIdx.x;
    int r = idx >> 7, c = idx & 127;
    size_t base = (size_t)r * 384;
    float ir = gi[base + c], iz = gi[base + 128 + c], in_ = gi[base + 256 + c];
    float hr = gh[base + c], hz = gh[base + 128 + c], hn = gh[base + 256 + c];
    float hv = h_in[idx];
    float rg = 1.f / (1.f + expf(-(ir + hr)));
    float zg = 1.f / (1.f + expf(-(iz + hz)));
    float ng = tanhf(in_ + rg * hn);
    h_out[idx] = (1.f - zg) * ng + zg * hv;
}

// ---------------------------------------------------------------------------
// q[Mx8] = H[Mx128] @ Wfc2[8x128]^T + b[8]
// ---------------------------------------------------------------------------
__global__ void fc2_kernel(const float* __restrict__ H, const float* __restrict__ W,
                           const float* __restrict__ bias, float* __restrict__ Q) {
    __shared__ float Hs[32][132];
    __shared__ float Ws[8][132];
    int tid = threadIdx.x;
    size_t r0 = (size_t)blockIdx.x * 32;

    for (int i = tid; i < 32 * 32; i += 256) {
        int r = i >> 5, c4 = (i & 31) << 2;
        *(float4*)&Hs[r][c4] = *(const float4*)&H[(r0 + r) * 128 + c4];
    }
    for (int i = tid; i < 8 * 32; i += 256) {
        int r = i >> 5, c4 = (i & 31) << 2;
        *(float4*)&Ws[r][c4] = *(const float4*)&W[r * 128 + c4];
    }
    __syncthreads();

    int rl = tid >> 3, a = tid & 7;
    float acc = 0.f;
#pragma unroll
    for (int k = 0; k < 128; k++) acc += Hs[rl][k] * Ws[a][k];
    Q[(r0 + rl) * 8 + a] = acc + bias[a];
}

// ---------------------------------------------------------------------------
extern "C" void kernel_launch(void* const* d_in, const int* in_sizes, int n_in,
                              void* d_out, int out_size) {
    const float* inputs   = (const float*)d_in[0];   // (102400, 128)
    const float* hidden   = (const float*)d_in[1];   // (2048, 50, 128)
    const float* norm_adj = (const float*)d_in[2];   // (50, 50)
    const float* w_gcn    = (const float*)d_in[3];   // (128, 128)
    const float* b_gcn    = (const float*)d_in[4];
    const float* w_ih     = (const float*)d_in[5];   // (384, 128)
    const float* b_ih     = (const float*)d_in[6];
    const float* w_hh     = (const float*)d_in[7];   // (384, 128)
    const float* b_hh     = (const float*)d_in[8];
    const float* w_fc2    = (const float*)d_in[9];   // (8, 128)
    const float* b_fc2    = (const float*)d_in[10];

    float* out = (float*)d_out;
    float* q_out = out;               // (102400, 8)
    float* h_out = out + QSIZE;       // (102400, 128)

    float *bufY, *gi, *gh;
    __nv_bfloat16 *xs, *hs, *wgs, *wihs, *whhs;
    cudaGetSymbolAddress((void**)&bufY, g_bufY);
    cudaGetSymbolAddress((void**)&gi, g_gi);
    cudaGetSymbolAddress((void**)&gh, g_gh);
    cudaGetSymbolAddress((void**)&xs, g_xs);
    cudaGetSymbolAddress((void**)&hs, g_hs);
    cudaGetSymbolAddress((void**)&wgs, g_wgs);
    cudaGetSymbolAddress((void**)&wihs, g_wihs);
    cudaGetSymbolAddress((void**)&whhs, g_whhs);

    cudaFuncSetAttribute(gemm_hmma, cudaFuncAttributeMaxDynamicSharedMemorySize, GEMM_SMEM);

    const int BIG4 = NROWS * 128 / 4;   // 3,276,800 float4s
    cvt_split<<<(BIG4 + 255) / 256, 256>>>(inputs, xs, BIG4);
    cvt_split<<<(BIG4 + 255) / 256, 256>>>(hidden, hs, BIG4);
    cvt_split<<<16, 256>>>(w_gcn, wgs, 128 * 128 / 4);
    cvt_split<<<48, 256>>>(w_ih, wihs, 384 * 128 / 4);
    cvt_split<<<48, 256>>>(w_hh, whhs, 384 * 128 / 4);

    const int MT = NROWS / 128;   // 800 row tiles

    // 3 GCN passes: Y = X @ Wg^T (HMMA, compensated), then X = relu(A@Y + b) (+split)
    for (int p = 0; p < 3; p++) {
        gemm_hmma<<<MT, 256, GEMM_SMEM>>>(xs, wgs, nullptr, bufY, 128, 1);
        adj_relu_cvt<<<NBATCH, 512>>>(bufY, norm_adj, b_gcn, xs);
    }

    // GRU gates
    gemm_hmma<<<MT, 256, GEMM_SMEM>>>(xs, wihs, b_ih, gi, 384, 3);
    gemm_hmma<<<MT, 256, GEMM_SMEM>>>(hs, whhs, b_hh, gh, 384, 3);
    gru_kernel<<<(NROWS * 128) / 256, 256>>>(gi, gh, hidden, h_out);

    // fc2 -> q
    fc2_kernel<<<NROWS / 32, 256>>>(h_out, w_fc2, b_fc2, q_out);
}